// round 16
// baseline (speedup 1.0000x reference)
#include <cuda_runtime.h>

#define NB   8
#define CIN  64
#define HID  128
#define HH   192
#define WW   192
#define PIX  (HH*WW)   /* 36864 */

typedef unsigned long long u64;

__device__ __forceinline__ u64 pack2(float lo, float hi) {
    u64 d;
    asm("mov.b64 %0, {%1,%2};" : "=l"(d)
        : "r"(__float_as_uint(lo)), "r"(__float_as_uint(hi)));
    return d;
}
__device__ __forceinline__ void unpack2(u64 v, float& lo, float& hi) {
    unsigned a, b;
    asm("mov.b64 {%0,%1}, %2;" : "=r"(a), "=r"(b) : "l"(v));
    lo = __uint_as_float(a); hi = __uint_as_float(b);
}
__device__ __forceinline__ u64 ffma2(u64 a, u64 b, u64 c) {
    u64 d;
    asm("fma.rn.f32x2 %0, %1, %2, %3;" : "=l"(d) : "l"(a), "l"(b), "l"(c));
    return d;
}

// scratch (allocation-guard-safe __device__ globals)
__device__ float g_xmean[NB * CIN];
__device__ float g_gg[NB * HID];
__device__ float g_dk[NB * HID * 9];
__device__ float g_h[(size_t)NB * HID * PIX];   // 151 MB intermediate

// ---------------------------------------------------------------------------
// K1: per-(b,c) mean of x (mean(h) = W_in @ mean(x) + b_in by linearity).
// ---------------------------------------------------------------------------
__global__ __launch_bounds__(256) void k_xmean(const float* __restrict__ x) {
    int bc = blockIdx.x;
    const float4* xp = (const float4*)(x + (size_t)bc * PIX);
    float s0 = 0.f, s1 = 0.f, s2 = 0.f, s3 = 0.f;
    int i = threadIdx.x;
    #pragma unroll 1
    for (; i + 768 < PIX / 4; i += 1024) {
        float4 a = xp[i],       bq = xp[i + 256];
        float4 c = xp[i + 512], d  = xp[i + 768];
        s0 += (a.x + a.y) + (a.z + a.w);
        s1 += (bq.x + bq.y) + (bq.z + bq.w);
        s2 += (c.x + c.y) + (c.z + c.w);
        s3 += (d.x + d.y) + (d.z + d.w);
    }
    for (; i < PIX / 4; i += 256) {
        float4 a = xp[i];
        s0 += (a.x + a.y) + (a.z + a.w);
    }
    float s = (s0 + s1) + (s2 + s3);
    __shared__ float red[256];
    red[threadIdx.x] = s;
    __syncthreads();
    for (int off = 128; off > 0; off >>= 1) {
        if (threadIdx.x < off) red[threadIdx.x] += red[threadIdx.x + off];
        __syncthreads();
    }
    if (threadIdx.x == 0) g_xmean[bc] = red[0] * (1.0f / PIX);
}

// ---------------------------------------------------------------------------
// K2a: hmean -> relu(wg1 @ hmean + bg1) = gg. 4 blocks.
// ---------------------------------------------------------------------------
__global__ __launch_bounds__(256) void k_genAB(
    const float* __restrict__ w_in, const float* __restrict__ b_in,
    const float* __restrict__ wg1,  const float* __restrict__ bg1) {
    __shared__ float hm[NB * HID];
    int tid = threadIdx.x;
    for (int idx = tid; idx < NB * HID; idx += 256) {
        int b = idx / HID, o = idx % HID;
        float s = b_in[o];
        #pragma unroll 16
        for (int c = 0; c < CIN; c++) s += w_in[o * CIN + c] * g_xmean[b * CIN + c];
        hm[idx] = s;
    }
    __syncthreads();
    int idx = blockIdx.x * 256 + tid;
    int b = idx / HID, j = idx % HID;
    float s = bg1[j];
    const float4* wr = (const float4*)&wg1[j * HID];
    const float4* hr = (const float4*)&hm[b * HID];
    #pragma unroll 8
    for (int o = 0; o < HID / 4; o++) {
        float4 w = wr[o], h = hr[o];
        s += w.x * h.x + w.y * h.y + w.z * h.z + w.w * h.w;
    }
    g_gg[idx] = s > 0.f ? s : 0.f;
}

// ---------------------------------------------------------------------------
// K2b: dk = wg2 @ gg + bg2. 36 blocks; wg2 staged coalesced; read once.
// ---------------------------------------------------------------------------
__global__ __launch_bounds__(256) void k_genC(
    const float* __restrict__ wg2, const float* __restrict__ bg2) {
    __shared__ float w2s[32 * 128];
    __shared__ float ggs[NB * HID];
    int tid = threadIdx.x;
    int m0 = blockIdx.x * 32;
    for (int idx = tid; idx < 32 * 128 / 4; idx += 256)
        *(float4*)&w2s[idx * 4] = *(const float4*)&wg2[(size_t)m0 * HID + idx * 4];
    for (int idx = tid; idx < NB * HID / 4; idx += 256)
        *(float4*)&ggs[idx * 4] = *(const float4*)&g_gg[idx * 4];
    __syncthreads();
    int ml = tid >> 3, b = tid & 7;
    float s = bg2[m0 + ml];
    #pragma unroll 8
    for (int j = 0; j < HID / 4; j++) {
        float4 w = *(const float4*)&w2s[ml * 128 + j * 4];
        float4 g = *(const float4*)&ggs[b * HID + j * 4];
        s += w.x * g.x + w.y * g.y + w.z * g.z + w.w * g.w;
    }
    g_dk[b * HID * 9 + m0 + ml] = s;
}

// ---------------------------------------------------------------------------
// K3: h = W_in @ x + b_in. 512 thr, 2 CTAs/SM. Pack-free inner loop:
// x as natural u64 px-pairs, weights pre-duplicated (w,w) in smem.
// wdup row = 130 u64 (128 hid channels + 2 pad).
// ---------------------------------------------------------------------------
#define PPX 128
#define WPR 130   /* wdup row pitch in u64: HID + 2 pad */

__global__ __launch_bounds__(512, 2) void k_proj(
    const float* __restrict__ x, const float* __restrict__ w_in,
    const float* __restrict__ b_in) {
    extern __shared__ float sp[];
    float* xs   = sp;                    // [64][128]  32768 B
    u64*   wdup = (u64*)(sp + 64 * PPX); // [64][130]u64  66560 B
    int b  = blockIdx.y;
    int p0 = blockIdx.x * PPX;
    int tid = threadIdx.x;

    // stage w dup'd (coalesced LDG over c)
    for (int idx = tid; idx < CIN * HID; idx += 512) {
        int o = idx >> 6, c = idx & 63;
        float w = w_in[o * CIN + c];
        wdup[c * WPR + o] = pack2(w, w);
    }
    // stage x tile
    for (int idx = tid; idx < CIN * (PPX / 4); idx += 512) {
        int c = idx >> 5, pg = (idx & 31) << 2;
        *(float4*)&xs[c * PPX + pg] =
            *(const float4*)&x[(size_t)(b * CIN + c) * PIX + p0 + pg];
    }
    __syncthreads();

    int och = (tid >> 5) * 8;   // warp-uniform, 16 groups x 8 hid-ch
    int pxg = tid & 31;         // 32 x 4px

    u64 acc[8][2];              // 8 ch x 2 px-pairs
    #pragma unroll
    for (int i = 0; i < 8; i++) {
        float bi = __ldg(&b_in[och + i]);
        acc[i][0] = pack2(bi, bi);
        acc[i][1] = acc[i][0];
    }

    #pragma unroll 8
    for (int c = 0; c < CIN; c++) {
        ulonglong2 xp = *(const ulonglong2*)&xs[c * PPX + pxg * 4];
        ulonglong2 wA = *(const ulonglong2*)&wdup[c * WPR + och];
        ulonglong2 wB = *(const ulonglong2*)&wdup[c * WPR + och + 2];
        ulonglong2 wC = *(const ulonglong2*)&wdup[c * WPR + och + 4];
        ulonglong2 wD = *(const ulonglong2*)&wdup[c * WPR + och + 6];
        acc[0][0] = ffma2(wA.x, xp.x, acc[0][0]);
        acc[0][1] = ffma2(wA.x, xp.y, acc[0][1]);
        acc[1][0] = ffma2(wA.y, xp.x, acc[1][0]);
        acc[1][1] = ffma2(wA.y, xp.y, acc[1][1]);
        acc[2][0] = ffma2(wB.x, xp.x, acc[2][0]);
        acc[2][1] = ffma2(wB.x, xp.y, acc[2][1]);
        acc[3][0] = ffma2(wB.y, xp.x, acc[3][0]);
        acc[3][1] = ffma2(wB.y, xp.y, acc[3][1]);
        acc[4][0] = ffma2(wC.x, xp.x, acc[4][0]);
        acc[4][1] = ffma2(wC.x, xp.y, acc[4][1]);
        acc[5][0] = ffma2(wC.y, xp.x, acc[5][0]);
        acc[5][1] = ffma2(wC.y, xp.y, acc[5][1]);
        acc[6][0] = ffma2(wD.x, xp.x, acc[6][0]);
        acc[6][1] = ffma2(wD.x, xp.y, acc[6][1]);
        acc[7][0] = ffma2(wD.y, xp.x, acc[7][0]);
        acc[7][1] = ffma2(wD.y, xp.y, acc[7][1]);
    }

    #pragma unroll
    for (int i = 0; i < 8; i++) {
        float4 v;
        unpack2(acc[i][0], v.x, v.y);
        unpack2(acc[i][1], v.z, v.w);
        *(float4*)&g_h[(size_t)(b * HID + och + i) * PIX + p0 + pxg * 4] = v;
    }
}

// ---------------------------------------------------------------------------
// K4: per-sample dw3x3 + LeakyReLU + out = W_out@y + b_out.
// 512 thr, 2 CTAs/SM. Out-proj pack-free (y natural pairs, w dup'd in smem,
// restaged per 64-ch half). Bias in acc init.
// ---------------------------------------------------------------------------
#define XROW 344   /* 34*10=340 used */
#define YROW 264   /* 256 used */
#define CHK  32

__global__ __launch_bounds__(512, 2) void k_dwout(
    const float* __restrict__ w_out, const float* __restrict__ b_out,
    float* __restrict__ out) {
    extern __shared__ float sd[];
    float* hsm  = sd;                        // [32][344]  44032B
    float* ylc  = hsm + CHK * XROW;          // [32][264]  33792B
    u64*   wdup = (u64*)(ylc + CHK * YROW);  // [64][66]u64 33792B (64-ch half)
    // total 111616 B -> 2 CTAs/SM

    int b   = blockIdx.z;
    int tx0 = blockIdx.x * 32;
    int ty0 = blockIdx.y * 8;
    int tid = threadIdx.x;
    int lane = tid & 31, wrp = tid >> 5;

    int och = (tid >> 6) * 8;   // 8 groups x 8 out-ch (warp-uniform)
    int pxg = tid & 63;         // 64 x 4px

    u64 acc[8][2];              // 8 out-ch x 2 px-pairs; bias in init
    #pragma unroll
    for (int i = 0; i < 8; i++) {
        float bo = __ldg(&b_out[och + i]);
        acc[i][0] = pack2(bo, bo);
        acc[i][1] = acc[i][0];
    }

    for (int cc = 0; cc < HID; cc += CHK) {
        __syncthreads();
        // restage dup'd w_out half at cc = 0 and 64
        if ((cc & 63) == 0) {
            for (int idx = tid; idx < 64 * 64; idx += 512) {
                int o = idx >> 6, c = idx & 63;
                float w = w_out[o * HID + cc + c];
                wdup[c * 66 + o] = pack2(w, w);
            }
        }
        // stage h halo chunk (zero-padded SAME)
        for (int idx = tid; idx < CHK * 340; idx += 512) {
            int c = idx / 340, hp = idx - c * 340;
            int hy = hp / 34,  hx = hp - hy * 34;
            int gy = ty0 + hy - 1, gx = tx0 + hx - 1;
            float v = 0.f;
            if (gy >= 0 && gy < HH && gx >= 0 && gx < WW)
                v = g_h[(size_t)(b * HID + cc + c) * PIX + gy * WW + gx];
            hsm[c * XROW + hp] = v;
        }
        __syncthreads();

        // ---- depthwise 3x3 + LeakyReLU: 16 warps x 2ch, rotating taps ----
        #pragma unroll
        for (int ii = 0; ii < 2; ii++) {
            int c = wrp * 2 + ii;
            float kr[9];
            #pragma unroll
            for (int j = 0; j < 9; j++)
                kr[j] = __ldg(&g_dk[(b * HID + cc + c) * 9 + j]);
            const float* hc = &hsm[c * XROW];
            float l0 = hc[lane],      c0 = hc[lane + 1],      r0 = hc[lane + 2];
            float l1 = hc[34 + lane], c1 = hc[34 + lane + 1], r1 = hc[34 + lane + 2];
            #pragma unroll
            for (int i = 0; i < 8; i++) {
                int rb = (i + 2) * 34 + lane;
                float l2 = hc[rb], c2 = hc[rb + 1], r2 = hc[rb + 2];
                float y = kr[0] * l0 + kr[1] * c0 + kr[2] * r0
                        + kr[3] * l1 + kr[4] * c1 + kr[5] * r1
                        + kr[6] * l2 + kr[7] * c2 + kr[8] * r2;
                ylc[c * YROW + i * 32 + lane] = y > 0.f ? y : 0.1f * y;
                l0 = l1; c0 = c1; r0 = r1;
                l1 = l2; c1 = c2; r1 = r2;
            }
        }
        __syncthreads();

        // ---- out-projection accumulate: pack-free ----
        int cw0 = cc & 32;   // offset within current wdup half
        #pragma unroll 4
        for (int c = 0; c < CHK; c++) {
            ulonglong2 yp = *(const ulonglong2*)&ylc[c * YROW + pxg * 4];
            ulonglong2 wA = *(const ulonglong2*)&wdup[(cw0 + c) * 66 + och];
            ulonglong2 wB = *(const ulonglong2*)&wdup[(cw0 + c) * 66 + och + 2];
            ulonglong2 wC = *(const ulonglong2*)&wdup[(cw0 + c) * 66 + och + 4];
            ulonglong2 wD = *(const ulonglong2*)&wdup[(cw0 + c) * 66 + och + 6];
            acc[0][0] = ffma2(wA.x, yp.x, acc[0][0]);
            acc[0][1] = ffma2(wA.x, yp.y, acc[0][1]);
            acc[1][0] = ffma2(wA.y, yp.x, acc[1][0]);
            acc[1][1] = ffma2(wA.y, yp.y, acc[1][1]);
            acc[2][0] = ffma2(wB.x, yp.x, acc[2][0]);
            acc[2][1] = ffma2(wB.x, yp.y, acc[2][1]);
            acc[3][0] = ffma2(wB.y, yp.x, acc[3][0]);
            acc[3][1] = ffma2(wB.y, yp.y, acc[3][1]);
            acc[4][0] = ffma2(wC.x, yp.x, acc[4][0]);
            acc[4][1] = ffma2(wC.x, yp.y, acc[4][1]);
            acc[5][0] = ffma2(wC.y, yp.x, acc[5][0]);
            acc[5][1] = ffma2(wC.y, yp.y, acc[5][1]);
            acc[6][0] = ffma2(wD.x, yp.x, acc[6][0]);
            acc[6][1] = ffma2(wD.x, yp.y, acc[6][1]);
            acc[7][0] = ffma2(wD.y, yp.x, acc[7][0]);
            acc[7][1] = ffma2(wD.y, yp.y, acc[7][1]);
        }
    }

    // write out: 8 ch x 4 px, coalesced
    int pxo = pxg * 4;
    int py = pxo >> 5, pxx = pxo & 31;
    #pragma unroll
    for (int i = 0; i < 8; i++) {
        float4 v;
        unpack2(acc[i][0], v.x, v.y);
        unpack2(acc[i][1], v.z, v.w);
        size_t base = (size_t)(b * CIN + och + i) * PIX + (ty0 + py) * WW + tx0 + pxx;
        *(float4*)&out[base] = v;
    }
}

// ---------------------------------------------------------------------------
extern "C" void kernel_launch(void* const* d_in, const int* in_sizes, int n_in,
                              void* d_out, int out_size) {
    const float* x     = (const float*)d_in[0];
    const float* w_in  = (const float*)d_in[1];
    const float* b_in  = (const float*)d_in[2];
    const float* wg1   = (const float*)d_in[3];
    const float* bg1   = (const float*)d_in[4];
    const float* wg2   = (const float*)d_in[5];
    const float* bg2   = (const float*)d_in[6];
    const float* w_out = (const float*)d_in[7];
    const float* b_out = (const float*)d_in[8];
    float* out = (float*)d_out;

    k_xmean<<<NB * CIN, 256>>>(x);
    k_genAB<<<4, 256>>>(w_in, b_in, wg1, bg1);
    k_genC<<<36, 256>>>(wg2, bg2);

    int smem_p = 64 * PPX * 4 + 64 * WPR * 8;   // 99328 B
    cudaFuncSetAttribute(k_proj, cudaFuncAttributeMaxDynamicSharedMemorySize, smem_p);
    k_proj<<<dim3(PIX / PPX, NB), 512, smem_p>>>(x, w_in, b_in);

    int smem_d = (CHK * XROW + CHK * YROW) * 4 + 64 * 66 * 8;   // 111616 B
    cudaFuncSetAttribute(k_dwout, cudaFuncAttributeMaxDynamicSharedMemorySize, smem_d);
    k_dwout<<<dim3(WW / 32, HH / 8, NB), 512, smem_d>>>(w_out, b_out, out);
}

// round 17
// speedup vs baseline: 1.6221x; 1.6221x over previous
#include <cuda_runtime.h>

#define NB   8
#define CIN  64
#define HID  128
#define HH   192
#define WW   192
#define PIX  (HH*WW)   /* 36864 */

typedef unsigned long long u64;

__device__ __forceinline__ u64 pack2(float lo, float hi) {
    u64 d;
    asm("mov.b64 %0, {%1,%2};" : "=l"(d)
        : "r"(__float_as_uint(lo)), "r"(__float_as_uint(hi)));
    return d;
}
__device__ __forceinline__ void unpack2(u64 v, float& lo, float& hi) {
    unsigned a, b;
    asm("mov.b64 {%0,%1}, %2;" : "=r"(a), "=r"(b) : "l"(v));
    lo = __uint_as_float(a); hi = __uint_as_float(b);
}
__device__ __forceinline__ u64 ffma2(u64 a, u64 b, u64 c) {
    u64 d;
    asm("fma.rn.f32x2 %0, %1, %2, %3;" : "=l"(d) : "l"(a), "l"(b), "l"(c));
    return d;
}
__device__ __forceinline__ void cp_async16(unsigned dst, const void* src) {
    asm volatile("cp.async.ca.shared.global [%0], [%1], 16;"
                 :: "r"(dst), "l"(src));
}
__device__ __forceinline__ void cp_commit() {
    asm volatile("cp.async.commit_group;");
}
__device__ __forceinline__ void cp_wait0() {
    asm volatile("cp.async.wait_group 0;");
}

// scratch (allocation-guard-safe __device__ globals)
__device__ float g_xmean[NB * CIN];
__device__ float g_gg[NB * HID];
__device__ float g_dk[NB * HID * 9];
__device__ float g_h[(size_t)NB * HID * PIX];   // 151 MB intermediate

// ---------------------------------------------------------------------------
// K1: per-(b,c) mean of x (mean(h) = W_in @ mean(x) + b_in by linearity).
// ---------------------------------------------------------------------------
__global__ __launch_bounds__(256) void k_xmean(const float* __restrict__ x) {
    int bc = blockIdx.x;
    const float4* xp = (const float4*)(x + (size_t)bc * PIX);
    float s0 = 0.f, s1 = 0.f, s2 = 0.f, s3 = 0.f;
    int i = threadIdx.x;
    #pragma unroll 1
    for (; i + 768 < PIX / 4; i += 1024) {
        float4 a = xp[i],       bq = xp[i + 256];
        float4 c = xp[i + 512], d  = xp[i + 768];
        s0 += (a.x + a.y) + (a.z + a.w);
        s1 += (bq.x + bq.y) + (bq.z + bq.w);
        s2 += (c.x + c.y) + (c.z + c.w);
        s3 += (d.x + d.y) + (d.z + d.w);
    }
    for (; i < PIX / 4; i += 256) {
        float4 a = xp[i];
        s0 += (a.x + a.y) + (a.z + a.w);
    }
    float s = (s0 + s1) + (s2 + s3);
    __shared__ float red[256];
    red[threadIdx.x] = s;
    __syncthreads();
    for (int off = 128; off > 0; off >>= 1) {
        if (threadIdx.x < off) red[threadIdx.x] += red[threadIdx.x + off];
        __syncthreads();
    }
    if (threadIdx.x == 0) g_xmean[bc] = red[0] * (1.0f / PIX);
}

// ---------------------------------------------------------------------------
// K2a: hmean -> relu(wg1 @ hmean + bg1) = gg. 4 blocks.
// ---------------------------------------------------------------------------
__global__ __launch_bounds__(256) void k_genAB(
    const float* __restrict__ w_in, const float* __restrict__ b_in,
    const float* __restrict__ wg1,  const float* __restrict__ bg1) {
    __shared__ float hm[NB * HID];
    int tid = threadIdx.x;
    for (int idx = tid; idx < NB * HID; idx += 256) {
        int b = idx / HID, o = idx % HID;
        float s = b_in[o];
        #pragma unroll 16
        for (int c = 0; c < CIN; c++) s += w_in[o * CIN + c] * g_xmean[b * CIN + c];
        hm[idx] = s;
    }
    __syncthreads();
    int idx = blockIdx.x * 256 + tid;
    int b = idx / HID, j = idx % HID;
    float s = bg1[j];
    const float4* wr = (const float4*)&wg1[j * HID];
    const float4* hr = (const float4*)&hm[b * HID];
    #pragma unroll 8
    for (int o = 0; o < HID / 4; o++) {
        float4 w = wr[o], h = hr[o];
        s += w.x * h.x + w.y * h.y + w.z * h.z + w.w * h.w;
    }
    g_gg[idx] = s > 0.f ? s : 0.f;
}

// ---------------------------------------------------------------------------
// K2b: dk = wg2 @ gg + bg2. 36 blocks; wg2 staged coalesced; read once.
// ---------------------------------------------------------------------------
__global__ __launch_bounds__(256) void k_genC(
    const float* __restrict__ wg2, const float* __restrict__ bg2) {
    __shared__ float w2s[32 * 128];
    __shared__ float ggs[NB * HID];
    int tid = threadIdx.x;
    int m0 = blockIdx.x * 32;
    for (int idx = tid; idx < 32 * 128 / 4; idx += 256)
        *(float4*)&w2s[idx * 4] = *(const float4*)&wg2[(size_t)m0 * HID + idx * 4];
    for (int idx = tid; idx < NB * HID / 4; idx += 256)
        *(float4*)&ggs[idx * 4] = *(const float4*)&g_gg[idx * 4];
    __syncthreads();
    int ml = tid >> 3, b = tid & 7;
    float s = bg2[m0 + ml];
    #pragma unroll 8
    for (int j = 0; j < HID / 4; j++) {
        float4 w = *(const float4*)&w2s[ml * 128 + j * 4];
        float4 g = *(const float4*)&ggs[b * HID + j * 4];
        s += w.x * g.x + w.y * g.y + w.z * g.z + w.w * g.w;
    }
    g_dk[b * HID * 9 + m0 + ml] = s;
}

// ---------------------------------------------------------------------------
// K3: h = W_in @ x + b_in. 1024 thr, R14 inner loop (w ch-pairs from smem,
// x dup via movs). 4 px-tiles per block, cp.async double-buffered x staging:
// tile t+1 copies in flight while tile t computes. w staged once per block.
// ---------------------------------------------------------------------------
#define PPX 256
#define NT  4

__global__ __launch_bounds__(1024, 1) void k_proj(
    const float* __restrict__ x, const float* __restrict__ w_in,
    const float* __restrict__ b_in) {
    extern __shared__ float sp[];
    float* xs0 = sp;                    // [64][256]
    float* xs1 = sp + 64 * PPX;         // [64][256]
    float* wsT = sp + 2 * 64 * PPX;     // [64][132]  w_in^T, [cin][hid]
    int b  = blockIdx.y;
    int pbase = blockIdx.x * (PPX * NT);
    int tid = threadIdx.x;

    // stage w^T once (coalesced LDG over hid)
    for (int idx = tid; idx < CIN * HID; idx += 1024) {
        int ch = idx & 127, c = idx >> 7;
        wsT[c * 132 + ch] = w_in[ch * CIN + c];
    }

    // prefetch tile 0
    {
        float* dst = xs0;
        for (int idx = tid; idx < 64 * 64; idx += 1024) {
            int c = idx >> 6, pg = (idx & 63) << 2;
            unsigned d = (unsigned)__cvta_generic_to_shared(&dst[c * PPX + pg]);
            cp_async16(d, &x[(size_t)(b * CIN + c) * PIX + pbase + pg]);
        }
        cp_commit();
    }

    int och = (tid >> 6) * 8;   // warp-uniform
    int pxg = tid & 63;

    for (int t = 0; t < NT; t++) {
        int p0 = pbase + t * PPX;
        float* xs = (t & 1) ? xs1 : xs0;
        cp_wait0();
        __syncthreads();
        // prefetch next tile into the other buffer (overlaps compute below)
        if (t + 1 < NT) {
            float* dst = (t & 1) ? xs0 : xs1;
            int pn = p0 + PPX;
            for (int idx = tid; idx < 64 * 64; idx += 1024) {
                int c = idx >> 6, pg = (idx & 63) << 2;
                unsigned d = (unsigned)__cvta_generic_to_shared(&dst[c * PPX + pg]);
                cp_async16(d, &x[(size_t)(b * CIN + c) * PIX + pn + pg]);
            }
            cp_commit();
        }

        u64 acc2[4][4];
        #pragma unroll
        for (int i = 0; i < 4; i++)
            #pragma unroll
            for (int j = 0; j < 4; j++) acc2[i][j] = 0ULL;

        #pragma unroll 8
        for (int c = 0; c < CIN; c++) {
            float4 xv = *(const float4*)&xs[c * PPX + pxg * 4];
            u64 yd0 = pack2(xv.x, xv.x), yd1 = pack2(xv.y, xv.y);
            u64 yd2 = pack2(xv.z, xv.z), yd3 = pack2(xv.w, xv.w);
            ulonglong2 wa = *(const ulonglong2*)&wsT[c * 132 + och];
            ulonglong2 wb = *(const ulonglong2*)&wsT[c * 132 + och + 4];
            acc2[0][0] = ffma2(wa.x, yd0, acc2[0][0]);
            acc2[0][1] = ffma2(wa.x, yd1, acc2[0][1]);
            acc2[0][2] = ffma2(wa.x, yd2, acc2[0][2]);
            acc2[0][3] = ffma2(wa.x, yd3, acc2[0][3]);
            acc2[1][0] = ffma2(wa.y, yd0, acc2[1][0]);
            acc2[1][1] = ffma2(wa.y, yd1, acc2[1][1]);
            acc2[1][2] = ffma2(wa.y, yd2, acc2[1][2]);
            acc2[1][3] = ffma2(wa.y, yd3, acc2[1][3]);
            acc2[2][0] = ffma2(wb.x, yd0, acc2[2][0]);
            acc2[2][1] = ffma2(wb.x, yd1, acc2[2][1]);
            acc2[2][2] = ffma2(wb.x, yd2, acc2[2][2]);
            acc2[2][3] = ffma2(wb.x, yd3, acc2[2][3]);
            acc2[3][0] = ffma2(wb.y, yd0, acc2[3][0]);
            acc2[3][1] = ffma2(wb.y, yd1, acc2[3][1]);
            acc2[3][2] = ffma2(wb.y, yd2, acc2[3][2]);
            acc2[3][3] = ffma2(wb.y, yd3, acc2[3][3]);
        }

        float vals[8][4];
        #pragma unroll
        for (int p = 0; p < 4; p++)
            #pragma unroll
            for (int j = 0; j < 4; j++)
                unpack2(acc2[p][j], vals[2 * p][j], vals[2 * p + 1][j]);

        #pragma unroll
        for (int i = 0; i < 8; i++) {
            float bo = __ldg(&b_in[och + i]);
            *(float4*)&g_h[(size_t)(b * HID + och + i) * PIX + p0 + pxg * 4] =
                make_float4(vals[i][0] + bo, vals[i][1] + bo,
                            vals[i][2] + bo, vals[i][3] + bo);
        }
        __syncthreads();
    }
}

// ---------------------------------------------------------------------------
// K4: per-sample dw3x3 + LeakyReLU + out = W_out@y + b_out.
// R14 verbatim: 512 thr, 2 CTAs/SM, w ch-pairs from smem, y dup via movs.
// ---------------------------------------------------------------------------
#define XROW 344   /* 34*10=340 used */
#define YROW 264   /* 256 used */
#define CHK  32

__global__ __launch_bounds__(512, 2) void k_dwout(
    const float* __restrict__ w_out, const float* __restrict__ b_out,
    float* __restrict__ out) {
    extern __shared__ float sd[];
    float* hsm = sd;                   // [32][344]
    float* ylc = hsm + CHK * XROW;     // [32][264]
    float* wt  = ylc + CHK * YROW;     // [128][68]  w_out^T
    // total (11008+8448+8704)*4 = 112640 B

    int b   = blockIdx.z;
    int tx0 = blockIdx.x * 32;
    int ty0 = blockIdx.y * 8;
    int tid = threadIdx.x;
    int lane = tid & 31, wrp = tid >> 5;

    for (int idx = tid; idx < CIN * HID; idx += 512) {
        int o = idx & 63, c = idx >> 6;
        wt[c * 68 + o] = w_out[o * HID + c];
    }

    int och = (tid >> 6) * 8;   // warp-uniform (8 groups x 8 out-ch)
    int pxg = tid & 63;

    u64 acc2[4][4];
    #pragma unroll
    for (int i = 0; i < 4; i++)
        #pragma unroll
        for (int j = 0; j < 4; j++) acc2[i][j] = 0ULL;

    for (int cc = 0; cc < HID; cc += CHK) {
        __syncthreads();
        // stage h halo chunk (zero-padded SAME)
        for (int idx = tid; idx < CHK * 340; idx += 512) {
            int c = idx / 340, hp = idx - c * 340;
            int hy = hp / 34,  hx = hp - hy * 34;
            int gy = ty0 + hy - 1, gx = tx0 + hx - 1;
            float v = 0.f;
            if (gy >= 0 && gy < HH && gx >= 0 && gx < WW)
                v = g_h[(size_t)(b * HID + cc + c) * PIX + gy * WW + gx];
            hsm[c * XROW + hp] = v;
        }
        __syncthreads();

        // ---- depthwise 3x3 + LeakyReLU: 16 warps x 2ch, rotating taps ----
        #pragma unroll
        for (int ii = 0; ii < 2; ii++) {
            int c = wrp * 2 + ii;
            float kr[9];
            #pragma unroll
            for (int j = 0; j < 9; j++)
                kr[j] = __ldg(&g_dk[(b * HID + cc + c) * 9 + j]);
            const float* hc = &hsm[c * XROW];
            float l0 = hc[lane],      c0 = hc[lane + 1],      r0 = hc[lane + 2];
            float l1 = hc[34 + lane], c1 = hc[34 + lane + 1], r1 = hc[34 + lane + 2];
            #pragma unroll
            for (int i = 0; i < 8; i++) {
                int rb = (i + 2) * 34 + lane;
                float l2 = hc[rb], c2 = hc[rb + 1], r2 = hc[rb + 2];
                float y = kr[0] * l0 + kr[1] * c0 + kr[2] * r0
                        + kr[3] * l1 + kr[4] * c1 + kr[5] * r1
                        + kr[6] * l2 + kr[7] * c2 + kr[8] * r2;
                ylc[c * YROW + i * 32 + lane] = y > 0.f ? y : 0.1f * y;
                l0 = l1; c0 = c1; r0 = r1;
                l1 = l2; c1 = c2; r1 = r2;
            }
        }
        __syncthreads();

        // ---- out-projection accumulate: 8ch x 4px, f32x2 ch-pairs ----
        #pragma unroll 4
        for (int c = 0; c < CHK; c++) {
            float4 y = *(const float4*)&ylc[c * YROW + pxg * 4];
            u64 yd0 = pack2(y.x, y.x), yd1 = pack2(y.y, y.y);
            u64 yd2 = pack2(y.z, y.z), yd3 = pack2(y.w, y.w);
            ulonglong2 wa = *(const ulonglong2*)&wt[(cc + c) * 68 + och];
            ulonglong2 wb = *(const ulonglong2*)&wt[(cc + c) * 68 + och + 4];
            acc2[0][0] = ffma2(wa.x, yd0, acc2[0][0]);
            acc2[0][1] = ffma2(wa.x, yd1, acc2[0][1]);
            acc2[0][2] = ffma2(wa.x, yd2, acc2[0][2]);
            acc2[0][3] = ffma2(wa.x, yd3, acc2[0][3]);
            acc2[1][0] = ffma2(wa.y, yd0, acc2[1][0]);
            acc2[1][1] = ffma2(wa.y, yd1, acc2[1][1]);
            acc2[1][2] = ffma2(wa.y, yd2, acc2[1][2]);
            acc2[1][3] = ffma2(wa.y, yd3, acc2[1][3]);
            acc2[2][0] = ffma2(wb.x, yd0, acc2[2][0]);
            acc2[2][1] = ffma2(wb.x, yd1, acc2[2][1]);
            acc2[2][2] = ffma2(wb.x, yd2, acc2[2][2]);
            acc2[2][3] = ffma2(wb.x, yd3, acc2[2][3]);
            acc2[3][0] = ffma2(wb.y, yd0, acc2[3][0]);
            acc2[3][1] = ffma2(wb.y, yd1, acc2[3][1]);
            acc2[3][2] = ffma2(wb.y, yd2, acc2[3][2]);
            acc2[3][3] = ffma2(wb.y, yd3, acc2[3][3]);
        }
    }

    // unpack + write out (+b_out): 8 ch x 4 px, coalesced
    float vals[8][4];
    #pragma unroll
    for (int p = 0; p < 4; p++)
        #pragma unroll
        for (int j = 0; j < 4; j++)
            unpack2(acc2[p][j], vals[2 * p][j], vals[2 * p + 1][j]);

    int pxo = pxg * 4;
    int py = pxo >> 5, pxx = pxo & 31;
    #pragma unroll
    for (int i = 0; i < 8; i++) {
        int o = och + i;
        float bo = __ldg(&b_out[o]);
        size_t base = (size_t)(b * CIN + o) * PIX + (ty0 + py) * WW + tx0 + pxx;
        *(float4*)&out[base] = make_float4(vals[i][0] + bo, vals[i][1] + bo,
                                           vals[i][2] + bo, vals[i][3] + bo);
    }
}

// ---------------------------------------------------------------------------
extern "C" void kernel_launch(void* const* d_in, const int* in_sizes, int n_in,
                              void* d_out, int out_size) {
    const float* x     = (const float*)d_in[0];
    const float* w_in  = (const float*)d_in[1];
    const float* b_in  = (const float*)d_in[2];
    const float* wg1   = (const float*)d_in[3];
    const float* bg1   = (const float*)d_in[4];
    const float* wg2   = (const float*)d_in[5];
    const float* bg2   = (const float*)d_in[6];
    const float* w_out = (const float*)d_in[7];
    const float* b_out = (const float*)d_in[8];
    float* out = (float*)d_out;

    k_xmean<<<NB * CIN, 256>>>(x);
    k_genAB<<<4, 256>>>(w_in, b_in, wg1, bg1);
    k_genC<<<36, 256>>>(wg2, bg2);

    int smem_p = (2 * 64 * PPX + 64 * 132) * 4;   // 164864 B
    cudaFuncSetAttribute(k_proj, cudaFuncAttributeMaxDynamicSharedMemorySize, smem_p);
    k_proj<<<dim3(PIX / (PPX * NT), NB), 1024, smem_p>>>(x, w_in, b_in);

    int smem_d = (CHK * XROW + CHK * YROW + 128 * 68) * 4;   // 112640 B
    cudaFuncSetAttribute(k_dwout, cudaFuncAttributeMaxDynamicSharedMemorySize, smem_d);
    k_dwout<<<dim3(WW / 32, HH / 8, NB), 512, smem_d>>>(w_out, b_out, out);
}